// round 2
// baseline (speedup 1.0000x reference)
#include <cuda_runtime.h>
#include <cuda_bf16.h>
#include <mma.h>
#include <math.h>

using namespace nvcuda;

// ---------------------------------------------------------------------------
// RiemannianGNN: 2-layer Poincare GNN.
//   per layer: t = (logmap(x) if layer>0 else x)*mask
//              msg = (t @ W)*mask
//              c   = (sum_k w[n,k]*msg[adj[n,k]])*mask
//              x   = relu(expmap(c)*mask)*mask
// Fusions: logmap of layer 1 fused into agg of layer 0.
// GEMM: tf32 WMMA (tensor cores), fp32 accumulate.
// ---------------------------------------------------------------------------

#define NMAX 50000
#define DD 128
#define KK 32

__device__ float g_msg[NMAX * DD];
__device__ float g_x[NMAX * DD];

// ---------------- tf32 WMMA GEMM: out[n,d] = (x[n,:] @ W)[d] * mask[n] -----
// block: 128 rows x 128 cols, 256 threads (8 warps), each warp 32x64.
#define GROWS 128
#define LDS 136   // padded leading dim (floats) to dodge bank conflicts

__global__ __launch_bounds__(256) void gemm_tf32_kernel(
    const float* __restrict__ x, const float* __restrict__ W,
    const float* __restrict__ mask, float* __restrict__ out,
    int N, int applyInMask)
{
    extern __shared__ float sm[];
    float* Ws = sm;                    // 128 x LDS
    float* xs = sm + DD * LDS;         // GROWS x LDS

    const int tid = threadIdx.x;
    const int n0 = blockIdx.x * GROWS;

    // load W (convert to tf32)
    for (int i = tid; i < DD * DD / 4; i += 256) {
        int r = i >> 5;        // /32 float4 per row
        int c4 = i & 31;
        float4 v = ((const float4*)W)[r * 32 + c4];
        float* dst = Ws + r * LDS + c4 * 4;
        dst[0] = wmma::__float_to_tf32(v.x);
        dst[1] = wmma::__float_to_tf32(v.y);
        dst[2] = wmma::__float_to_tf32(v.z);
        dst[3] = wmma::__float_to_tf32(v.w);
    }
    // load x rows (convert to tf32), zero-pad, optional input mask
    for (int i = tid; i < GROWS * DD / 4; i += 256) {
        int r = i >> 5;
        int c4 = i & 31;
        int n = n0 + r;
        float4 v = make_float4(0.f, 0.f, 0.f, 0.f);
        if (n < N) {
            v = ((const float4*)x)[n * 32 + c4];
            if (applyInMask) {
                float m = mask[n];
                v.x *= m; v.y *= m; v.z *= m; v.w *= m;
            }
        }
        float* dst = xs + r * LDS + c4 * 4;
        dst[0] = wmma::__float_to_tf32(v.x);
        dst[1] = wmma::__float_to_tf32(v.y);
        dst[2] = wmma::__float_to_tf32(v.z);
        dst[3] = wmma::__float_to_tf32(v.w);
    }
    __syncthreads();

    const int w = tid >> 5;
    const int rowWarp = w >> 1;    // 0..3 -> rows rowWarp*32
    const int colWarp = w & 1;     // 0..1 -> cols colWarp*64

    wmma::fragment<wmma::matrix_a, 16, 16, 8, wmma::precision::tf32, wmma::row_major> aF[2];
    wmma::fragment<wmma::matrix_b, 16, 16, 8, wmma::precision::tf32, wmma::row_major> bF[4];
    wmma::fragment<wmma::accumulator, 16, 16, 8, float> acc[2][4];

    #pragma unroll
    for (int i = 0; i < 2; i++)
        #pragma unroll
        for (int j = 0; j < 4; j++)
            wmma::fill_fragment(acc[i][j], 0.0f);

    #pragma unroll
    for (int ks = 0; ks < DD / 8; ks++) {
        const int kOff = ks * 8;
        #pragma unroll
        for (int i = 0; i < 2; i++)
            wmma::load_matrix_sync(aF[i], xs + (rowWarp * 32 + i * 16) * LDS + kOff, LDS);
        #pragma unroll
        for (int j = 0; j < 4; j++)
            wmma::load_matrix_sync(bF[j], Ws + kOff * LDS + colWarp * 64 + j * 16, LDS);
        #pragma unroll
        for (int i = 0; i < 2; i++)
            #pragma unroll
            for (int j = 0; j < 4; j++)
                wmma::mma_sync(acc[i][j], aF[i], bF[j], acc[i][j]);
    }

    // park results in xs (done reading it), then masked float4 write-out
    __syncthreads();
    #pragma unroll
    for (int i = 0; i < 2; i++)
        #pragma unroll
        for (int j = 0; j < 4; j++)
            wmma::store_matrix_sync(
                xs + (rowWarp * 32 + i * 16) * LDS + colWarp * 64 + j * 16,
                acc[i][j], LDS, wmma::mem_row_major);
    __syncthreads();

    for (int i = tid; i < GROWS * 32; i += 256) {
        int r = i >> 5;
        int c4 = i & 31;
        int n = n0 + r;
        if (n < N) {
            float m = mask[n];
            float4 v = *(float4*)(xs + r * LDS + c4 * 4);
            v.x *= m; v.y *= m; v.z *= m; v.w *= m;
            ((float4*)out)[n * 32 + c4] = v;
        }
    }
}

// ---------------- Aggregation + expmap + relu (+ fused logmap) -------------
// one warp per node; lane l holds cols 4l..4l+3
__global__ __launch_bounds__(256) void agg_kernel(
    const float* __restrict__ msg, const int* __restrict__ adj,
    const float* __restrict__ wgt, const float* __restrict__ mask,
    float* __restrict__ out, int N, int fuseLogmap)
{
    const int warp = (blockIdx.x * blockDim.x + threadIdx.x) >> 5;
    const int lane = threadIdx.x & 31;
    if (warp >= N) return;

    const int   myIdx = adj[warp * KK + lane];
    const float myW   = wgt[warp * KK + lane];

    float4 acc = make_float4(0.f, 0.f, 0.f, 0.f);
    #pragma unroll
    for (int j = 0; j < KK; j++) {
        int   nb = __shfl_sync(0xffffffffu, myIdx, j);
        float wj = __shfl_sync(0xffffffffu, myW,   j);
        float4 v = __ldg(((const float4*)(msg + (size_t)nb * DD)) + lane);
        acc.x = fmaf(wj, v.x, acc.x);
        acc.y = fmaf(wj, v.y, acc.y);
        acc.z = fmaf(wj, v.z, acc.z);
        acc.w = fmaf(wj, v.w, acc.w);
    }

    const float m = mask[warp];
    acc.x *= m; acc.y *= m; acc.z *= m; acc.w *= m;

    // expmap_zero
    float ss = acc.x * acc.x + acc.y * acc.y + acc.z * acc.z + acc.w * acc.w;
    #pragma unroll
    for (int o = 16; o > 0; o >>= 1) ss += __shfl_xor_sync(0xffffffffu, ss, o);
    float n1 = sqrtf(ss);
    float nc1 = fminf(fmaxf(n1, 1e-5f), 15.0f);
    float s1 = tanhf(nc1) / fmaxf(n1, 1e-5f);
    s1 *= m;

    float4 e;
    e.x = acc.x * s1; e.y = acc.y * s1; e.z = acc.z * s1; e.w = acc.w * s1;
    e.x = fmaxf(e.x, 0.f) * m; e.y = fmaxf(e.y, 0.f) * m;
    e.z = fmaxf(e.z, 0.f) * m; e.w = fmaxf(e.w, 0.f) * m;

    if (fuseLogmap) {
        float ss2 = e.x * e.x + e.y * e.y + e.z * e.z + e.w * e.w;
        #pragma unroll
        for (int o = 16; o > 0; o >>= 1) ss2 += __shfl_xor_sync(0xffffffffu, ss2, o);
        float n2 = sqrtf(ss2);
        float nc2 = fminf(fmaxf(n2, 1e-5f), 1.0f - 1e-5f);
        float s2 = atanhf(nc2) / fmaxf(n2, 1e-5f);
        s2 *= m;
        e.x *= s2; e.y *= s2; e.z *= s2; e.w *= s2;
    }

    ((float4*)out)[warp * 32 + lane] = e;
}

// ---------------------------------------------------------------------------

extern "C" void kernel_launch(void* const* d_in, const int* in_sizes, int n_in,
                              void* d_out, int out_size)
{
    const float* node_repr = (const float*)d_in[0];   // [N,128]
    const int*   adj_mat   = (const int*)  d_in[1];   // [N,32]
    const float* weight    = (const float*)d_in[2];   // [N,32]
    const float* mask      = (const float*)d_in[3];   // [N,1]
    const float* msg_w     = (const float*)d_in[4];   // [2,128,128]
    float*       out       = (float*)d_out;

    const int N = in_sizes[0] / DD;

    float* msg; float* xbuf;
    cudaGetSymbolAddress((void**)&msg,  g_msg);
    cudaGetSymbolAddress((void**)&xbuf, g_x);

    const int smemBytes = (DD * LDS + GROWS * LDS) * sizeof(float);  // ~136 KB
    static int attrSet = 0;
    if (!attrSet) {
        cudaFuncSetAttribute(gemm_tf32_kernel,
                             cudaFuncAttributeMaxDynamicSharedMemorySize, smemBytes);
        attrSet = 1;
    }

    const int gemmBlocks = (N + GROWS - 1) / GROWS;
    const int aggBlocks  = (N * 32 + 255) / 256;

    const float* W0 = msg_w;
    const float* W1 = msg_w + DD * DD;

    gemm_tf32_kernel<<<gemmBlocks, 256, smemBytes>>>(node_repr, W0, mask, msg, N, 1);
    agg_kernel     <<<aggBlocks, 256>>>(msg, adj_mat, weight, mask, xbuf, N, 1);
    gemm_tf32_kernel<<<gemmBlocks, 256, smemBytes>>>(xbuf, W1, mask, msg, N, 0);
    agg_kernel     <<<aggBlocks, 256>>>(msg, adj_mat, weight, mask, out, N, 0);
}